// round 15
// baseline (speedup 1.0000x reference)
#include <cuda_runtime.h>

#define NN 100000
#define EE 1000000
#define CAP 64

// ---------------- static device scratch ----------------
__device__ __align__(16) int   g_cnt[NN];
__device__ __align__(16) int   g_adj[NN * CAP];

__device__ __align__(16) float g_h[NN * 64];
__device__ __align__(16) float g_x1[NN * 64];
__device__ __align__(16) float g_xl1[NN * 144];
__device__ __align__(16) float g_xr1[NN * 144];
__device__ __align__(16) float g_x2[NN * 144];
__device__ __align__(16) float g_xl2[NN * 64];
__device__ __align__(16) float g_xr2[NN * 64];

__device__ __forceinline__ float lrelu(float v) { return v > 0.f ? v : 0.2f * v; }

// ---- packed f32x2 helpers (FFMA2 is PTX-only on sm_103a) ----
__device__ __forceinline__ void fma2(unsigned long long& a,
                                     unsigned long long x, unsigned long long w) {
    asm("fma.rn.f32x2 %0, %1, %2, %0;" : "+l"(a) : "l"(x), "l"(w));
}
__device__ __forceinline__ unsigned long long pack2(float lo, float hi) {
    unsigned long long r;
    asm("mov.b64 %0, {%1, %2};" : "=l"(r) : "f"(lo), "f"(hi));
    return r;
}
__device__ __forceinline__ float f2lo(unsigned long long a) {
    return __uint_as_float((unsigned)(a & 0xffffffffull));
}
__device__ __forceinline__ float f2hi(unsigned long long a) {
    return __uint_as_float((unsigned)(a >> 32));
}

// ---------------- zero counters ----------------
__global__ void k_zero() {
    int i = blockIdx.x * blockDim.x + threadIdx.x;
    if (i < NN) g_cnt[i] = 0;
}

// ---------------- build padded adjacency (edge_index is int32) ----------------
__global__ void k_build(const int* __restrict__ ei) {
    int e = blockIdx.x * blockDim.x + threadIdx.x;
    if (e >= EE) return;
    int s = ei[e];
    int d = ei[EE + e];
    int pos = atomicAdd(&g_cnt[d], 1);
    g_adj[d * CAP + pos] = s;
}

// ---------------- SSGConv: warp per dst, dinv inline ----------------
__global__ void k_ssg(const float* __restrict__ x) {
    int wid = threadIdx.x >> 5, lane = threadIdx.x & 31;
    int d = blockIdx.x * 8 + wid;
    if (d >= NN) return;
    int cntd = g_cnt[d];
    float dd = rsqrtf((float)(cntd + 1));
    float x0 = x[d * 64 + lane];
    float x1 = x[d * 64 + lane + 32];
    float acc0 = 0.f, acc1 = 0.f;
    int beg = d * CAP, end = beg + cntd;
    for (int i = beg; i < end; i += 8) {
        int n = end - i; if (n > 8) n = 8;
        float v0[8], v1[8], dv[8];
        #pragma unroll
        for (int k = 0; k < 8; k++) if (k < n) {
            int s = g_adj[i + k];
            v0[k] = x[s * 64 + lane];
            v1[k] = x[s * 64 + lane + 32];
            dv[k] = rsqrtf((float)(g_cnt[s] + 1));
        }
        #pragma unroll
        for (int k = 0; k < 8; k++) if (k < n) {
            acc0 += v0[k] * dv[k];
            acc1 += v1[k] * dv[k];
        }
    }
    g_h[d * 64 + lane]      = 0.5f * x0 + 0.5f * (x0 * dd * dd + dd * acc0);
    g_h[d * 64 + lane + 32] = 0.5f * x1 + 0.5f * (x1 * dd * dd + dd * acc1);
}

// ---------------- GEMM: FFMA2, CPT=4, duplicated-X smem (LDS.64, no movs) ----------------
// Per k per thread: 1 LDS.128 (w) + RPT LDS.64 (x dup, broadcast) + 2*RPT FFMA2.
// X staged in KS slices as (x,x) pairs; W resident (WFULL) or staged per slice.
template <int SEL, int K, int M, int NT, int RPT, int CHUNK, int KS, bool WFULL>
__global__ void __launch_bounds__(NT) gemm_bias(const float* __restrict__ W,
                                                const float* __restrict__ b) {
    const float* X;
    float* Y;
    if constexpr (SEL == 0)      { X = g_h;  Y = g_x1;  }
    else if constexpr (SEL == 1) { X = g_x1; Y = g_xl1; }
    else if constexpr (SEL == 2) { X = g_x1; Y = g_xr1; }
    else if constexpr (SEL == 3) { X = g_x2; Y = g_xl2; }
    else                         { X = g_x2; Y = g_xr2; }

    constexpr int TC = M / 4;
    constexpr int TR = NT / TC;
    constexpr int ROWS = TR * RPT;
    constexpr int KSP = KS + 2;       // pad in 8B units
    constexpr int K4S = KS / 4;
    constexpr int NST = K / KS;

    __shared__ float Ws[(WFULL ? K : KS) * M];
    __shared__ unsigned long long Xs2[ROWS * KSP];

    if constexpr (WFULL) {
        for (int i = threadIdx.x; i < K * M / 4; i += NT)
            *(float4*)&Ws[i * 4] = *(const float4*)&W[i * 4];
    }

    int tc = threadIdx.x % TC;
    int tr = threadIdx.x / TC;
    unsigned long long bp0 = pack2(b[tc * 4 + 0], b[tc * 4 + 1]);
    unsigned long long bp1 = pack2(b[tc * 4 + 2], b[tc * 4 + 3]);

    #pragma unroll
    for (int ch = 0; ch < CHUNK; ch++) {
        int row0 = (blockIdx.x * CHUNK + ch) * ROWS;
        if (row0 >= NN) break;

        unsigned long long acc[RPT][2];
        #pragma unroll
        for (int rr = 0; rr < RPT; rr++) { acc[rr][0] = bp0; acc[rr][1] = bp1; }

        #pragma unroll
        for (int st = 0; st < NST; st++) {
            int k0 = st * KS;
            __syncthreads();
            if constexpr (!WFULL) {
                for (int i = threadIdx.x; i < KS * M / 4; i += NT)
                    *(float4*)&Ws[i * 4] = *(const float4*)&W[k0 * M + i * 4];
            }
            for (int i4 = threadIdx.x; i4 < ROWS * K4S; i4 += NT) {
                int r = i4 / K4S, c4 = i4 - r * K4S;
                int gr = row0 + r;
                if (gr >= NN) gr = NN - 1;
                float4 v = *(const float4*)&X[gr * K + k0 + c4 * 4];
                unsigned long long* p = &Xs2[r * KSP + c4 * 4];
                p[0] = pack2(v.x, v.x);
                p[1] = pack2(v.y, v.y);
                p[2] = pack2(v.z, v.z);
                p[3] = pack2(v.w, v.w);
            }
            __syncthreads();

            #pragma unroll 4
            for (int k = 0; k < KS; k++) {
                int kw = WFULL ? (k0 + k) : k;
                ulonglong2 wv = *(const ulonglong2*)&Ws[kw * M + tc * 4];
                #pragma unroll
                for (int rr = 0; rr < RPT; rr++) {
                    unsigned long long xd = Xs2[(tr * RPT + rr) * KSP + k];
                    fma2(acc[rr][0], xd, wv.x);
                    fma2(acc[rr][1], xd, wv.y);
                }
            }
        }
        #pragma unroll
        for (int rr = 0; rr < RPT; rr++) {
            int r = row0 + tr * RPT + rr;
            if (r < NN) {
                float4 o;
                o.x = f2lo(acc[rr][0]); o.y = f2hi(acc[rr][0]);
                o.z = f2lo(acc[rr][1]); o.w = f2hi(acc[rr][1]);
                *(float4*)&Y[r * M + tc * 4] = o;
            }
        }
    }
}

// ---------------- fused GATv2 layer 1 (block version) ----------------
__global__ void k_gat1(const float* __restrict__ att, const float* __restrict__ bias) {
    int d = blockIdx.x, c = threadIdx.x;   // 144 threads
    int h = c / 12;
    __shared__ float prod[8][144];
    __shared__ float wsh[8][12];
    __shared__ float dshf[12];

    float attc = __ldg(&att[c]);
    float xrc  = g_xr1[d * 144 + c];
    float xld  = g_xl1[d * 144 + c];

    int beg = d * CAP, end = beg + g_cnt[d];

    prod[0][c] = lrelu(xld + xrc) * attc;
    __syncthreads();
    if (c < 12) {
        float s = 0.f;
        #pragma unroll
        for (int j = 0; j < 12; j++) s += prod[0][c * 12 + j];
        wsh[0][c] = __expf(s);
    }
    __syncthreads();
    float acc = wsh[0][h] * xld;
    float den = (c < 12) ? wsh[0][c] : 0.f;

    for (int i = beg; i < end; i += 8) {
        int n = end - i; if (n > 8) n = 8;
        float xls[8];
        #pragma unroll
        for (int k = 0; k < 8; k++) if (k < n) {
            int s = g_adj[i + k];
            xls[k] = g_xl1[s * 144 + c];
        }
        __syncthreads();
        #pragma unroll
        for (int k = 0; k < 8; k++) if (k < n)
            prod[k][c] = lrelu(xls[k] + xrc) * attc;
        __syncthreads();
        if (c < 12 * n) {
            int k = c / 12, hh = c - k * 12;
            float s = 0.f;
            #pragma unroll
            for (int j = 0; j < 12; j++) s += prod[k][hh * 12 + j];
            wsh[k][hh] = __expf(s);
        }
        __syncthreads();
        #pragma unroll
        for (int k = 0; k < 8; k++) if (k < n)
            acc += wsh[k][h] * xls[k];
        if (c < 12) {
            #pragma unroll
            for (int k = 0; k < 8; k++) if (k < n) den += wsh[k][c];
        }
    }
    if (c < 12) dshf[c] = den;
    __syncthreads();
    g_x2[d * 144 + c] = acc / (dshf[h] + 1e-16f) + bias[c];
}

// ---------------- fused GATv2 layer 2: warp per dst, sync-free, batch 8 ----------------
__global__ void k_gat2(const float* __restrict__ att, const float* __restrict__ bias,
                       float* __restrict__ out) {
    int wid = threadIdx.x >> 5, lane = threadIdx.x & 31;
    int d = blockIdx.x * 8 + wid;
    if (d >= NN) return;

    float a0 = __ldg(&att[lane]);
    float a1 = __ldg(&att[lane + 32]);
    float r0 = g_xr2[d * 64 + lane];
    float r1 = g_xr2[d * 64 + lane + 32];
    float l0 = g_xl2[d * 64 + lane];
    float l1 = g_xl2[d * 64 + lane + 32];

    float p = lrelu(l0 + r0) * a0 + lrelu(l1 + r1) * a1;
    #pragma unroll
    for (int o = 16; o > 0; o >>= 1) p += __shfl_xor_sync(0xffffffffu, p, o);
    float w = __expf(p);
    float den = w;
    float acc0 = w * l0, acc1 = w * l1;

    int beg = d * CAP, end = beg + g_cnt[d];
    for (int i = beg; i < end; i += 8) {
        int n = end - i; if (n > 8) n = 8;
        float x0[8], x1[8];
        #pragma unroll
        for (int k = 0; k < 8; k++) if (k < n) {
            int s = g_adj[i + k];
            x0[k] = g_xl2[s * 64 + lane];
            x1[k] = g_xl2[s * 64 + lane + 32];
        }
        #pragma unroll
        for (int k = 0; k < 8; k++) if (k < n) {
            float q = lrelu(x0[k] + r0) * a0 + lrelu(x1[k] + r1) * a1;
            #pragma unroll
            for (int o = 16; o > 0; o >>= 1) q += __shfl_xor_sync(0xffffffffu, q, o);
            float ww = __expf(q);
            den += ww;
            acc0 += ww * x0[k];
            acc1 += ww * x1[k];
        }
    }
    float inv = 1.f / (den + 1e-16f);
    out[d * 64 + lane]      = acc0 * inv + __ldg(&bias[lane]);
    out[d * 64 + lane + 32] = acc1 * inv + __ldg(&bias[lane + 32]);
}

// ---------------- launch ----------------
extern "C" void kernel_launch(void* const* d_in, const int* in_sizes, int n_in,
                              void* d_out, int out_size) {
    const float* features = (const float*)d_in[0];
    const int*   edge_idx = (const int*)d_in[1];
    const float* W_ssg = (const float*)d_in[2];
    const float* b_ssg = (const float*)d_in[3];
    const float* W1l   = (const float*)d_in[4];
    const float* b1l   = (const float*)d_in[5];
    const float* W1r   = (const float*)d_in[6];
    const float* b1r   = (const float*)d_in[7];
    const float* att1  = (const float*)d_in[8];
    const float* bias1 = (const float*)d_in[9];
    const float* W2l   = (const float*)d_in[10];
    const float* b2l   = (const float*)d_in[11];
    const float* W2r   = (const float*)d_in[12];
    const float* b2r   = (const float*)d_in[13];
    const float* att2  = (const float*)d_in[14];
    const float* bias2 = (const float*)d_in[15];
    float* out = (float*)d_out;

    const int WB = (NN + 7) / 8;

    // allow max smem carveout so more GEMM blocks can co-reside
    cudaFuncSetAttribute((const void*)gemm_bias<0, 64, 64, 128, 8, 6, 32, true>,
                         cudaFuncAttributePreferredSharedMemoryCarveout, 100);
    cudaFuncSetAttribute((const void*)gemm_bias<1, 64, 144, 144, 8, 8, 32, false>,
                         cudaFuncAttributePreferredSharedMemoryCarveout, 100);
    cudaFuncSetAttribute((const void*)gemm_bias<2, 64, 144, 144, 8, 8, 32, false>,
                         cudaFuncAttributePreferredSharedMemoryCarveout, 100);
    cudaFuncSetAttribute((const void*)gemm_bias<3, 144, 64, 128, 8, 4, 48, false>,
                         cudaFuncAttributePreferredSharedMemoryCarveout, 100);
    cudaFuncSetAttribute((const void*)gemm_bias<4, 144, 64, 128, 8, 4, 48, false>,
                         cudaFuncAttributePreferredSharedMemoryCarveout, 100);

    // adjacency build
    k_zero<<<(NN + 255) / 256, 256>>>();
    k_build<<<(EE + 255) / 256, 256>>>(edge_idx);

    // SSGConv — gemm0 is the 4th launch (ncu sample window)
    k_ssg<<<WB, 256>>>(features);

    // SEL K M NT RPT CHUNK KS WFULL   rows/block = (NT/(M/4))*RPT*CHUNK
    gemm_bias<0, 64, 64, 128, 8, 6, 32, true>
        <<<(NN + 383) / 384, 128>>>(W_ssg, b_ssg);                 // 384 rows, 33.4KB

    // GATv2 layer 1
    gemm_bias<1, 64, 144, 144, 8, 8, 32, false>
        <<<(NN + 255) / 256, 144>>>(W1l, b1l);                     // 256 rows, 27.1KB
    gemm_bias<2, 64, 144, 144, 8, 8, 32, false>
        <<<(NN + 255) / 256, 144>>>(W1r, b1r);
    k_gat1<<<NN, 144>>>(att1, bias1);

    // GATv2 layer 2
    gemm_bias<3, 144, 64, 128, 8, 4, 48, false>
        <<<(NN + 255) / 256, 128>>>(W2l, b2l);                     // 256 rows, 37.9KB
    gemm_bias<4, 144, 64, 128, 8, 4, 48, false>
        <<<(NN + 255) / 256, 128>>>(W2r, b2r);
    k_gat2<<<WB, 256>>>(att2, bias2, out);
}

// round 16
// speedup vs baseline: 1.1358x; 1.1358x over previous
#include <cuda_runtime.h>

#define NN 100000
#define EE 1000000
#define CAP 64

// ---------------- static device scratch ----------------
__device__ __align__(16) int   g_cnt[NN];
__device__ __align__(16) int   g_adj[NN * CAP];

__device__ __align__(16) float g_h[NN * 64];
__device__ __align__(16) float g_x1[NN * 64];
__device__ __align__(16) float g_xl1[NN * 144];
__device__ __align__(16) float g_xr1[NN * 144];
__device__ __align__(16) float g_x2[NN * 144];
__device__ __align__(16) float g_xl2[NN * 64];
__device__ __align__(16) float g_xr2[NN * 64];

__device__ __forceinline__ float lrelu(float v) { return v > 0.f ? v : 0.2f * v; }

// ---- packed f32x2 helpers (FFMA2 is PTX-only on sm_103a) ----
__device__ __forceinline__ void fma2(unsigned long long& a,
                                     unsigned long long x, unsigned long long w) {
    asm("fma.rn.f32x2 %0, %1, %2, %0;" : "+l"(a) : "l"(x), "l"(w));
}
__device__ __forceinline__ unsigned long long pack2(float lo, float hi) {
    unsigned long long r;
    asm("mov.b64 %0, {%1, %2};" : "=l"(r) : "f"(lo), "f"(hi));
    return r;
}
__device__ __forceinline__ float f2lo(unsigned long long a) {
    return __uint_as_float((unsigned)(a & 0xffffffffull));
}
__device__ __forceinline__ float f2hi(unsigned long long a) {
    return __uint_as_float((unsigned)(a >> 32));
}

// ---------------- zero counters ----------------
__global__ void k_zero() {
    int i = blockIdx.x * blockDim.x + threadIdx.x;
    if (i < NN) g_cnt[i] = 0;
}

// ---------------- build padded adjacency (edge_index is int32) ----------------
__global__ void k_build(const int* __restrict__ ei) {
    int e = blockIdx.x * blockDim.x + threadIdx.x;
    if (e >= EE) return;
    int s = ei[e];
    int d = ei[EE + e];
    int pos = atomicAdd(&g_cnt[d], 1);
    g_adj[d * CAP + pos] = s;
}

// ---------------- SSGConv: warp per dst, dinv inline ----------------
__global__ void k_ssg(const float* __restrict__ x) {
    int wid = threadIdx.x >> 5, lane = threadIdx.x & 31;
    int d = blockIdx.x * 8 + wid;
    if (d >= NN) return;
    int cntd = g_cnt[d];
    float dd = rsqrtf((float)(cntd + 1));
    float x0 = x[d * 64 + lane];
    float x1 = x[d * 64 + lane + 32];
    float acc0 = 0.f, acc1 = 0.f;
    int beg = d * CAP, end = beg + cntd;
    for (int i = beg; i < end; i += 8) {
        int n = end - i; if (n > 8) n = 8;
        float v0[8], v1[8], dv[8];
        #pragma unroll
        for (int k = 0; k < 8; k++) if (k < n) {
            int s = g_adj[i + k];
            v0[k] = x[s * 64 + lane];
            v1[k] = x[s * 64 + lane + 32];
            dv[k] = rsqrtf((float)(g_cnt[s] + 1));
        }
        #pragma unroll
        for (int k = 0; k < 8; k++) if (k < n) {
            acc0 += v0[k] * dv[k];
            acc1 += v1[k] * dv[k];
        }
    }
    g_h[d * 64 + lane]      = 0.5f * x0 + 0.5f * (x0 * dd * dd + dd * acc0);
    g_h[d * 64 + lane + 32] = 0.5f * x1 + 0.5f * (x1 * dd * dd + dd * acc1);
}

// ---------------- GEMM (round-13 body): FFMA2, CPT=4, k-staged X, W resident ----------
// DUAL: blockIdx.y selects (W0,b0,Y=l) or (W1,b1,Y=r). Body otherwise identical.
template <int SEL, int K, int M, int NT, int RPT, int CHUNK, int KS>
__global__ void __launch_bounds__(NT) gemm_dual(const float* __restrict__ W0,
                                                const float* __restrict__ b0,
                                                const float* __restrict__ W1,
                                                const float* __restrict__ b1) {
    const float* X;
    float* Y;
    if constexpr (SEL == 0)      { X = g_h;  Y = g_x1; }
    else if constexpr (SEL == 1) { X = g_x1; Y = blockIdx.y ? g_xr1 : g_xl1; }
    else                         { X = g_x2; Y = blockIdx.y ? g_xr2 : g_xl2; }
    const float* W = blockIdx.y ? W1 : W0;
    const float* b = blockIdx.y ? b1 : b0;

    constexpr int TC = M / 4;
    constexpr int TR = NT / TC;
    constexpr int ROWS = TR * RPT;
    constexpr int KSP = KS + 4;
    constexpr int K4S = KS / 4;
    constexpr int NST = K / KS;

    __shared__ float Ws[K * M];
    __shared__ float Xs[ROWS * KSP];

    for (int i = threadIdx.x; i < K * M / 4; i += NT)
        *(float4*)&Ws[i * 4] = *(const float4*)&W[i * 4];

    int tc = threadIdx.x % TC;
    int tr = threadIdx.x / TC;
    unsigned long long bp0 = pack2(b[tc * 4 + 0], b[tc * 4 + 1]);
    unsigned long long bp1 = pack2(b[tc * 4 + 2], b[tc * 4 + 3]);

    #pragma unroll
    for (int ch = 0; ch < CHUNK; ch++) {
        int row0 = (blockIdx.x * CHUNK + ch) * ROWS;
        if (row0 >= NN) break;

        unsigned long long acc[RPT][2];
        #pragma unroll
        for (int rr = 0; rr < RPT; rr++) { acc[rr][0] = bp0; acc[rr][1] = bp1; }

        #pragma unroll
        for (int st = 0; st < NST; st++) {
            int k0 = st * KS;
            __syncthreads();
            for (int i4 = threadIdx.x; i4 < ROWS * K4S; i4 += NT) {
                int r = i4 / K4S, c4 = i4 - r * K4S;
                int gr = row0 + r;
                if (gr >= NN) gr = NN - 1;
                *(float4*)&Xs[r * KSP + c4 * 4] =
                    *(const float4*)&X[gr * K + k0 + c4 * 4];
            }
            __syncthreads();

            #pragma unroll 4
            for (int k = 0; k < KS; k++) {
                ulonglong2 wv = *(const ulonglong2*)&Ws[(k0 + k) * M + tc * 4];
                #pragma unroll
                for (int rr = 0; rr < RPT; rr++) {
                    float xv = Xs[(tr * RPT + rr) * KSP + k];
                    unsigned long long xd = pack2(xv, xv);
                    fma2(acc[rr][0], xd, wv.x);
                    fma2(acc[rr][1], xd, wv.y);
                }
            }
        }
        #pragma unroll
        for (int rr = 0; rr < RPT; rr++) {
            int r = row0 + tr * RPT + rr;
            if (r < NN) {
                float4 o;
                o.x = f2lo(acc[rr][0]); o.y = f2hi(acc[rr][0]);
                o.z = f2lo(acc[rr][1]); o.w = f2hi(acc[rr][1]);
                *(float4*)&Y[r * M + tc * 4] = o;
            }
        }
    }
}

// ---------------- fused GATv2 layer 1 (block version) ----------------
__global__ void k_gat1(const float* __restrict__ att, const float* __restrict__ bias) {
    int d = blockIdx.x, c = threadIdx.x;   // 144 threads
    int h = c / 12;
    __shared__ float prod[8][144];
    __shared__ float wsh[8][12];
    __shared__ float dshf[12];

    float attc = __ldg(&att[c]);
    float xrc  = g_xr1[d * 144 + c];
    float xld  = g_xl1[d * 144 + c];

    int beg = d * CAP, end = beg + g_cnt[d];

    prod[0][c] = lrelu(xld + xrc) * attc;
    __syncthreads();
    if (c < 12) {
        float s = 0.f;
        #pragma unroll
        for (int j = 0; j < 12; j++) s += prod[0][c * 12 + j];
        wsh[0][c] = __expf(s);
    }
    __syncthreads();
    float acc = wsh[0][h] * xld;
    float den = (c < 12) ? wsh[0][c] : 0.f;

    for (int i = beg; i < end; i += 8) {
        int n = end - i; if (n > 8) n = 8;
        float xls[8];
        #pragma unroll
        for (int k = 0; k < 8; k++) if (k < n) {
            int s = g_adj[i + k];
            xls[k] = g_xl1[s * 144 + c];
        }
        __syncthreads();
        #pragma unroll
        for (int k = 0; k < 8; k++) if (k < n)
            prod[k][c] = lrelu(xls[k] + xrc) * attc;
        __syncthreads();
        if (c < 12 * n) {
            int k = c / 12, hh = c - k * 12;
            float s = 0.f;
            #pragma unroll
            for (int j = 0; j < 12; j++) s += prod[k][hh * 12 + j];
            wsh[k][hh] = __expf(s);
        }
        __syncthreads();
        #pragma unroll
        for (int k = 0; k < 8; k++) if (k < n)
            acc += wsh[k][h] * xls[k];
        if (c < 12) {
            #pragma unroll
            for (int k = 0; k < 8; k++) if (k < n) den += wsh[k][c];
        }
    }
    if (c < 12) dshf[c] = den;
    __syncthreads();
    g_x2[d * 144 + c] = acc / (dshf[h] + 1e-16f) + bias[c];
}

// ---------------- fused GATv2 layer 2: warp per dst, sync-free, batch 8 ----------------
__global__ void k_gat2(const float* __restrict__ att, const float* __restrict__ bias,
                       float* __restrict__ out) {
    int wid = threadIdx.x >> 5, lane = threadIdx.x & 31;
    int d = blockIdx.x * 8 + wid;
    if (d >= NN) return;

    float a0 = __ldg(&att[lane]);
    float a1 = __ldg(&att[lane + 32]);
    float r0 = g_xr2[d * 64 + lane];
    float r1 = g_xr2[d * 64 + lane + 32];
    float l0 = g_xl2[d * 64 + lane];
    float l1 = g_xl2[d * 64 + lane + 32];

    float p = lrelu(l0 + r0) * a0 + lrelu(l1 + r1) * a1;
    #pragma unroll
    for (int o = 16; o > 0; o >>= 1) p += __shfl_xor_sync(0xffffffffu, p, o);
    float w = __expf(p);
    float den = w;
    float acc0 = w * l0, acc1 = w * l1;

    int beg = d * CAP, end = beg + g_cnt[d];
    for (int i = beg; i < end; i += 8) {
        int n = end - i; if (n > 8) n = 8;
        float x0[8], x1[8];
        #pragma unroll
        for (int k = 0; k < 8; k++) if (k < n) {
            int s = g_adj[i + k];
            x0[k] = g_xl2[s * 64 + lane];
            x1[k] = g_xl2[s * 64 + lane + 32];
        }
        #pragma unroll
        for (int k = 0; k < 8; k++) if (k < n) {
            float q = lrelu(x0[k] + r0) * a0 + lrelu(x1[k] + r1) * a1;
            #pragma unroll
            for (int o = 16; o > 0; o >>= 1) q += __shfl_xor_sync(0xffffffffu, q, o);
            float ww = __expf(q);
            den += ww;
            acc0 += ww * x0[k];
            acc1 += ww * x1[k];
        }
    }
    float inv = 1.f / (den + 1e-16f);
    out[d * 64 + lane]      = acc0 * inv + __ldg(&bias[lane]);
    out[d * 64 + lane + 32] = acc1 * inv + __ldg(&bias[lane + 32]);
}

// ---------------- launch ----------------
extern "C" void kernel_launch(void* const* d_in, const int* in_sizes, int n_in,
                              void* d_out, int out_size) {
    const float* features = (const float*)d_in[0];
    const int*   edge_idx = (const int*)d_in[1];
    const float* W_ssg = (const float*)d_in[2];
    const float* b_ssg = (const float*)d_in[3];
    const float* W1l   = (const float*)d_in[4];
    const float* b1l   = (const float*)d_in[5];
    const float* W1r   = (const float*)d_in[6];
    const float* b1r   = (const float*)d_in[7];
    const float* att1  = (const float*)d_in[8];
    const float* bias1 = (const float*)d_in[9];
    const float* W2l   = (const float*)d_in[10];
    const float* b2l   = (const float*)d_in[11];
    const float* W2r   = (const float*)d_in[12];
    const float* b2r   = (const float*)d_in[13];
    const float* att2  = (const float*)d_in[14];
    const float* bias2 = (const float*)d_in[15];
    float* out = (float*)d_out;

    const int WB = (NN + 7) / 8;

    // adjacency build
    k_zero<<<(NN + 255) / 256, 256>>>();
    k_build<<<(EE + 255) / 256, 256>>>(edge_idx);

    // SSGConv — gemm0 is the 4th launch (ncu sample window)
    k_ssg<<<WB, 256>>>(features);

    // round-13 GEMM configs, pairs fused on blockIdx.y
    // SEL K M NT RPT CHUNK KS    rows/block = (NT/(M/4))*RPT*CHUNK
    gemm_dual<0, 64, 64, 192, 8, 3, 64>
        <<<dim3((NN + 287) / 288, 1), 192>>>(W_ssg, b_ssg, W_ssg, b_ssg);   // 288 rows

    // GATv2 layer 1: l and r in one launch
    gemm_dual<1, 64, 144, 144, 8, 8, 64>
        <<<dim3((NN + 255) / 256, 2), 144>>>(W1l, b1l, W1r, b1r);           // 256 rows
    k_gat1<<<NN, 144>>>(att1, bias1);

    // GATv2 layer 2: l and r in one launch (K=144: X staged in 4 slices of 36)
    gemm_dual<2, 144, 64, 128, 8, 4, 36>
        <<<dim3((NN + 255) / 256, 2), 128>>>(W2l, b2l, W2r, b2r);           // 256 rows
    k_gat2<<<WB, 256>>>(att2, bias2, out);
}